// round 16
// baseline (speedup 1.0000x reference)
#include <cuda_runtime.h>
#include <cuda_fp16.h>
#include <math.h>
#include <stdint.h>

// Problem constants
#define Bsz 8
#define Ssz 2048
#define Dsz 1024
#define Hh  8
#define HDi 128
#define Pp  32
#define Msz (Bsz*Ssz)   // 16384

// Scratch (static device arrays — no allocation)
__device__ __half g_xh[(size_t)Msz*Dsz];       // 32 MB  x in fp16
__device__ __half g_headsh[(size_t)Msz*Dsz];   // 32 MB  heads fp16 (B,S,H*HD)
__device__ __half g_wph[(size_t)Dsz*Dsz];      // 2 MB   W_proj fp16
__device__ __half g_woh[(size_t)Dsz*Dsz];      // 2 MB   Wo fp16
__device__ float  g_partial[Bsz*32*Dsz];       // 32 row-chunks of 64 rows per batch
__device__ float  g_coef[Bsz*Hh*Hh];

// ---------------- float -> half converts ----------------
__global__ void f2h_kernel(const float* __restrict__ src, __half* __restrict__ dst) {
    int i = blockIdx.x * 256 + threadIdx.x;     // float4 index
    float4 v = reinterpret_cast<const float4*>(src)[i];
    __half2* d = reinterpret_cast<__half2*>(dst);
    d[2*i]   = __floats2half2_rn(v.x, v.y);
    d[2*i+1] = __floats2half2_rn(v.z, v.w);
}
// both weights in one launch: blocks [0,1024) -> W_proj, [1024,2048) -> Wo
__global__ void f2h_w_kernel(const float* __restrict__ s0, __half* __restrict__ d0,
                             const float* __restrict__ s1, __half* __restrict__ d1) {
    int blk = blockIdx.x;
    const float* src = (blk < 1024) ? s0 : s1;
    __half* dst      = (blk < 1024) ? d0 : d1;
    int i = (blk & 1023) * 256 + threadIdx.x;
    float4 v = reinterpret_cast<const float4*>(src)[i];
    __half2* d = reinterpret_cast<__half2*>(dst);
    d[2*i]   = __floats2half2_rn(v.x, v.y);
    d[2*i+1] = __floats2half2_rn(v.z, v.w);
}

// ====== fp16 TC GEMM: 128x128x64 block, 64x32 warp, mbarrier free-running 3-ring ======
// C[m,n] = sum_k A[m,k]*B[n,k]  (NT, fp16 operands in gmem)
// EPI==1: C half  = acc * cospi(e0[n]);  also emits column partial sums -> g_partial
// EPI==2: C float = acc + e0[n] + half2float(e1h[m,n])
#define NST 3                             // ring stages
#define BKH 64                            // K halves per stage
#define LDW 36                            // padded row stride in 32-bit words
#define STW (128*LDW)                     // words per array per stage (4608)
#define BAR_OFF ((NST*2*STW + 128) * 4)   // byte offset of mbarriers
#define GSM (BAR_OFF + 48)                // + 6 mbarriers = 111152 B

__device__ __forceinline__ void cp16(uint32_t s, const void* g) {
    asm volatile("cp.async.cg.shared.global [%0], [%1], 16;\n" :: "r"(s), "l"(g));
}
__device__ __forceinline__ void ldsm4(uint32_t& r0, uint32_t& r1, uint32_t& r2, uint32_t& r3,
                                      uint32_t addr) {
    asm volatile("ldmatrix.sync.aligned.m8n8.x4.shared.b16 {%0,%1,%2,%3}, [%4];"
                 : "=r"(r0), "=r"(r1), "=r"(r2), "=r"(r3) : "r"(addr));
}
#define MBAR_INIT(a, c) \
    asm volatile("mbarrier.init.shared.b64 [%0], %1;" :: "r"(a), "r"(c) : "memory")
#define MBAR_ARRIVE(a) \
    asm volatile("mbarrier.arrive.shared.b64 _, [%0];" :: "r"(a) : "memory")
#define CP_MBAR_ARRIVE(a) \
    asm volatile("cp.async.mbarrier.arrive.noinc.shared.b64 [%0];" :: "r"(a) : "memory")
__device__ __forceinline__ void mbar_wait(uint32_t addr, uint32_t parity) {
    asm volatile(
        "{\n\t.reg .pred P;\n\t"
        "W%=:\n\t"
        "mbarrier.try_wait.parity.shared.b64 P, [%0], %1;\n\t"
        "@P bra D%=;\n\t"
        "bra W%=;\n\t"
        "D%=:\n\t}"
        :: "r"(addr), "r"(parity) : "memory");
}

template<int EPI, typename OutT>
__global__ void __launch_bounds__(256, 2) gemm_h(
    const __half* __restrict__ A, const __half* __restrict__ Bm,
    OutT* __restrict__ C, const float* __restrict__ e0,
    const __half* __restrict__ e1h)
{
    extern __shared__ uint32_t sm[];
    float* vec = reinterpret_cast<float*>(sm + NST * 2 * STW);

    const int tid  = threadIdx.x;
    const int lane = tid & 31;
    const int w    = tid >> 5;
    const int g    = lane >> 2;
    const int tg   = lane & 3;
    const int wm   = (w >> 2) * 64;
    const int wn   = (w & 3) * 32;
    const int bm   = blockIdx.y * 128;
    const int bn   = blockIdx.x * 128;

    const uint32_t smb  = (uint32_t)__cvta_generic_to_shared(sm);
    const uint32_t barb = smb + BAR_OFF;          // full[s]=barb+8s, empty[s]=barb+24+8s

    if (tid == 0) {
        #pragma unroll
        for (int s = 0; s < NST; s++) {
            MBAR_INIT(barb + s * 8, 256);
            MBAR_INIT(barb + 24 + s * 8, 256);
        }
    }
    if (tid < 128) {
        float v = e0[bn + tid];
        vec[tid] = (EPI == 1) ? cospif(v) : v;
    }
    __syncthreads();   // only block-wide sync

    // loader: 1024 16B-chunks per array per stage; 4 per thread
    auto load_stage = [&](int kt, int s) {
        const uint32_t sA = smb + (uint32_t)(s * 2 * STW) * 4;
        const uint32_t sB = sA + (uint32_t)STW * 4;
        #pragma unroll
        for (int l = 0; l < 4; l++) {
            const int chunk = tid + l * 256;
            const int r = chunk >> 3;
            const int c = chunk & 7;
            const uint32_t so = (uint32_t)(r * LDW + c * 4) * 4;
            const size_t ko = (size_t)kt * BKH + c * 8;
            cp16(sA + so, A  + (size_t)(bm + r) * Dsz + ko);
            cp16(sB + so, Bm + (size_t)(bn + r) * Dsz + ko);
        }
    };

    // ldmatrix per-lane word offsets
    const int l8  = lane & 7;
    const int grp = lane >> 3;   // 0..3
    uint32_t aoff[4], boff[2];
    #pragma unroll
    for (int mf = 0; mf < 4; mf++) {
        const int row = wm + mf * 16 + l8 + (grp & 1) * 8;
        aoff[mf] = (uint32_t)(row * LDW + (grp >> 1) * 4) * 4;
    }
    #pragma unroll
    for (int p = 0; p < 2; p++) {
        const int row = wn + p * 16 + l8 + (grp >> 1) * 8;
        boff[p] = (uint32_t)(row * LDW + (grp & 1) * 4) * 4;
    }

    float acc[4][4][4];
    #pragma unroll
    for (int i = 0; i < 4; i++)
        #pragma unroll
        for (int j = 0; j < 4; j++)
            #pragma unroll
            for (int q = 0; q < 4; q++) acc[i][j][q] = 0.f;

    // prologue
    load_stage(0, 0); CP_MBAR_ARRIVE(barb + 0 * 8);
    load_stage(1, 1); CP_MBAR_ARRIVE(barb + 1 * 8);

    for (int kt = 0; kt < 16; kt++) {
        const int s = kt % NST;
        mbar_wait(barb + s * 8, (kt / NST) & 1);       // full[s]

        const uint32_t stA = smb + (uint32_t)(s * 2 * STW) * 4;
        const uint32_t stB = stA + (uint32_t)STW * 4;

        #pragma unroll
        for (int kk = 0; kk < 4; kk++) {
            const uint32_t kbb = kk * 32;
            uint32_t a[4][4], b[4][2];
            #pragma unroll
            for (int mf = 0; mf < 4; mf++)
                ldsm4(a[mf][0], a[mf][1], a[mf][2], a[mf][3], stA + aoff[mf] + kbb);
            #pragma unroll
            for (int p = 0; p < 2; p++)
                ldsm4(b[2*p][0], b[2*p][1], b[2*p+1][0], b[2*p+1][1], stB + boff[p] + kbb);
            #pragma unroll
            for (int mf = 0; mf < 4; mf++)
                #pragma unroll
                for (int nf = 0; nf < 4; nf++) {
                    asm volatile(
                        "mma.sync.aligned.m16n8k16.row.col.f32.f16.f16.f32 "
                        "{%0,%1,%2,%3}, {%4,%5,%6,%7}, {%8,%9}, {%0,%1,%2,%3};\n"
                        : "+f"(acc[mf][nf][0]), "+f"(acc[mf][nf][1]),
                          "+f"(acc[mf][nf][2]), "+f"(acc[mf][nf][3])
                        : "r"(a[mf][0]), "r"(a[mf][1]), "r"(a[mf][2]), "r"(a[mf][3]),
                          "r"(b[nf][0]), "r"(b[nf][1]));
                }
        }

        MBAR_ARRIVE(barb + 24 + s * 8);                // empty[s]

        const int kl = kt + 2;
        if (kl < 16) {
            const int sl = kl % NST;
            if (kl >= NST)
                mbar_wait(barb + 24 + sl * 8, ((kl / NST) - 1) & 1);
            load_stage(kl, sl);
            CP_MBAR_ARRIVE(barb + sl * 8);
        }
    }

    // ---- epilogue ----
    #pragma unroll
    for (int mf = 0; mf < 4; mf++) {
        const int r0 = bm + wm + mf * 16 + g;
        #pragma unroll
        for (int nf = 0; nf < 4; nf++) {
            const int cl = wn + nf * 8 + 2 * tg;
            const int cg = bn + cl;
            const float s0 = vec[cl], s1 = vec[cl + 1];
            if (EPI == 1) {
                __half2* Ch = reinterpret_cast<__half2*>(C);
                __half2 h0 = __floats2half2_rn(acc[mf][nf][0] * s0, acc[mf][nf][1] * s1);
                __half2 h1 = __floats2half2_rn(acc[mf][nf][2] * s0, acc[mf][nf][3] * s1);
                Ch[((size_t)r0 * Dsz + cg) >> 1]       = h0;
                Ch[((size_t)(r0 + 8) * Dsz + cg) >> 1] = h1;
            } else {
                float2 x0 = __half22float2(
                    *reinterpret_cast<const __half2*>(&e1h[(size_t)r0 * Dsz + cg]));
                float2 x1 = __half22float2(
                    *reinterpret_cast<const __half2*>(&e1h[(size_t)(r0 + 8) * Dsz + cg]));
                float2 v0, v1;
                v0.x = acc[mf][nf][0] + s0 + x0.x; v0.y = acc[mf][nf][1] + s1 + x0.y;
                v1.x = acc[mf][nf][2] + s0 + x1.x; v1.y = acc[mf][nf][3] + s1 + x1.y;
                *reinterpret_cast<float2*>(&((float*)C)[(size_t)r0 * Dsz + cg])       = v0;
                *reinterpret_cast<float2*>(&((float*)C)[(size_t)(r0 + 8) * Dsz + cg]) = v1;
            }
        }
    }

    if (EPI == 1) {
        // ---- fused hm partial sums: per-column sums of this warp's 64 rows ----
        // thread covers 8 rows (4 mf x {g, g+8}); reduce over g via shfl (stride 4,8,16)
        #pragma unroll
        for (int nf = 0; nf < 4; nf++) {
            const int cl = wn + nf * 8 + 2 * tg;
            float c0 = 0.f, c1 = 0.f;
            #pragma unroll
            for (int mf = 0; mf < 4; mf++) {
                c0 += acc[mf][nf][0] + acc[mf][nf][2];
                c1 += acc[mf][nf][1] + acc[mf][nf][3];
            }
            c0 *= vec[cl]; c1 *= vec[cl + 1];
            #pragma unroll
            for (int o = 4; o < 32; o <<= 1) {
                c0 += __shfl_xor_sync(0xffffffffu, c0, o);
                c1 += __shfl_xor_sync(0xffffffffu, c1, o);
            }
            if (g == 0) {   // lanes 0..3 hold full 64-row sums
                const int b      = bm >> 11;                       // batch
                const int chunk  = ((bm & 2047) >> 7) * 2 + (wm >> 6);  // 0..31
                float* dst = &g_partial[((size_t)(b * 32 + chunk)) * Dsz + bn + cl];
                dst[0] = c0;
                dst[1] = c1;
            }
        }
    }
}

// ---------------- pv + coef fused: grid Bsz, 256 threads ----------------
__global__ void pv_coef_kernel(const float* __restrict__ Wp, const float* __restrict__ bp,
                               const float* __restrict__ w1, const float* __restrict__ b1,
                               const float* __restrict__ w2, const float* __restrict__ b2)
{
    __shared__ float hm_s[Dsz];
    __shared__ float pm_s[Hh * Pp];
    const int b = blockIdx.x;
    const int t = threadIdx.x;

    // hm: reduce 32 row-chunks for 1024 dims
    #pragma unroll
    for (int i = 0; i < 4; i++) {
        const int dim = t + i * 256;
        float s = 0.f;
        #pragma unroll
        for (int ch = 0; ch < 32; ch++)
            s += g_partial[((size_t)(b * 32 + ch)) * Dsz + dim];
        hm_s[dim] = s * (1.0f / Ssz);
    }
    __syncthreads();

    // pv[h,p] = tanh(hm[h,:] . Wp[h,p,:] + bp), then normalize per h (warp = h)
    {
        const int h = t >> 5, p = t & 31;
        const float* hr = &hm_s[h * HDi];
        const float* wr = &Wp[(size_t)(h * Pp + p) * HDi];
        float s = 0.f;
        #pragma unroll 8
        for (int e = 0; e < HDi; e++) s += hr[e] * wr[e];
        float pv = tanhf(s + bp[h * Pp + p]);
        float sq = pv * pv;
        #pragma unroll
        for (int o = 16; o > 0; o >>= 1) sq += __shfl_xor_sync(0xffffffffu, sq, o);
        float inv = 1.0f / fmaxf(sqrtf(sq), 1e-12f);
        pm_s[t] = pv * inv;
    }
    __syncthreads();

    if (t < Hh * Hh) {
        const int i = t >> 3, j = t & 7;
        const float* pi = &pm_s[i * Pp];
        const float* pj = &pm_s[j * Pp];
        float d = 0.f;
        #pragma unroll
        for (int p = 0; p < Pp; p++) d += pi[p] * pj[p];
        float accv = b2[0];
        #pragma unroll
        for (int k = 0; k < 16; k++) {
            float hx = d * w1[k] + b1[k];
            float gg = 0.5f * hx * (1.0f + erff(hx * 0.70710678118654752f));
            accv += gg * w2[k];
        }
        float sp = fmaxf(accv, 0.f) + log1pf(expf(-fabsf(accv)));
        g_coef[b * 64 + t] = (i == j) ? 0.f : 0.1f / (1.0f + sp);
    }
}

// ---------------- in-place cross-head mix on fp16 heads ----------------
__global__ void mix_kernel() {
    __shared__ float cs[64];
    int m0 = blockIdx.x * 2;
    int b = m0 / Ssz;
    int t = threadIdx.x;
    if (t < 64) cs[t] = g_coef[b * 64 + t];
    __syncthreads();
    int lr = t >> 7, e = t & 127;
    int m = m0 + lr;
    int s = m & (Ssz - 1);
    float scale = (float)(s + 1) * (1.0f / (float)Ssz);
    __half* row = &g_headsh[(size_t)m * Dsz + e];
    float v[8];
    #pragma unroll
    for (int j = 0; j < 8; j++) v[j] = __half2float(row[j * HDi]);
    #pragma unroll
    for (int i = 0; i < 8; i++) {
        float a = 0.f;
        #pragma unroll
        for (int j = 0; j < 8; j++) a += cs[i * 8 + j] * v[j];
        row[i * HDi] = __float2half(v[i] + scale * a);
    }
}

// ---------------- in-place LayerNorm over D on d_out ----------------
__global__ void ln_kernel(float* __restrict__ y,
                          const float* __restrict__ g, const float* __restrict__ bb)
{
    int m = blockIdx.x;
    int t = threadIdx.x;
    float4 v = *reinterpret_cast<float4*>(&y[(size_t)m * Dsz + t * 4]);
    float s = v.x + v.y + v.z + v.w;
    float q = v.x * v.x + v.y * v.y + v.z * v.z + v.w * v.w;
    __shared__ float ss[8], qq[8];
    #pragma unroll
    for (int o = 16; o > 0; o >>= 1) {
        s += __shfl_down_sync(0xffffffffu, s, o);
        q += __shfl_down_sync(0xffffffffu, q, o);
    }
    if ((t & 31) == 0) { ss[t >> 5] = s; qq[t >> 5] = q; }
    __syncthreads();
    if (t < 8) {
        s = ss[t]; q = qq[t];
        #pragma unroll
        for (int o = 4; o > 0; o >>= 1) {
            s += __shfl_down_sync(0xffu, s, o);
            q += __shfl_down_sync(0xffu, q, o);
        }
        if (t == 0) { ss[0] = s; qq[0] = q; }
    }
    __syncthreads();
    float mu  = ss[0] * (1.0f / Dsz);
    float var = qq[0] * (1.0f / Dsz) - mu * mu;
    float inv = rsqrtf(var + 1e-5f);
    float4 gg = *reinterpret_cast<const float4*>(&g[t * 4]);
    float4 bv = *reinterpret_cast<const float4*>(&bb[t * 4]);
    v.x = (v.x - mu) * inv * gg.x + bv.x;
    v.y = (v.y - mu) * inv * gg.y + bv.y;
    v.z = (v.z - mu) * inv * gg.z + bv.z;
    v.w = (v.w - mu) * inv * gg.w + bv.w;
    *reinterpret_cast<float4*>(&y[(size_t)m * Dsz + t * 4]) = v;
}

// ======================= launch =======================
extern "C" void kernel_launch(void* const* d_in, const int* in_sizes, int n_in,
                              void* d_out, int out_size)
{
    const float* x      = (const float*)d_in[0];
    const float* W_proj = (const float*)d_in[1];
    const float* freqs  = (const float*)d_in[2];
    const float* Wp     = (const float*)d_in[3];
    const float* bp     = (const float*)d_in[4];
    const float* w1     = (const float*)d_in[5];
    const float* b1     = (const float*)d_in[6];
    const float* w2     = (const float*)d_in[7];
    const float* b2     = (const float*)d_in[8];
    const float* Wo     = (const float*)d_in[9];
    const float* bo     = (const float*)d_in[10];
    const float* ln_g   = (const float*)d_in[11];
    const float* ln_b   = (const float*)d_in[12];
    float* out = (float*)d_out;

    __half *xh = nullptr, *headsh = nullptr, *wph = nullptr, *woh = nullptr;
    cudaGetSymbolAddress((void**)&xh, g_xh);
    cudaGetSymbolAddress((void**)&headsh, g_headsh);
    cudaGetSymbolAddress((void**)&wph, g_wph);
    cudaGetSymbolAddress((void**)&woh, g_woh);

    cudaFuncSetAttribute(gemm_h<1, __half>, cudaFuncAttributeMaxDynamicSharedMemorySize, GSM);
    cudaFuncSetAttribute(gemm_h<2, float>,  cudaFuncAttributeMaxDynamicSharedMemorySize, GSM);

    // converts (x; both weights in one launch)
    f2h_kernel<<<(Msz * Dsz) / 4 / 256, 256>>>(x, xh);
    f2h_w_kernel<<<2048, 256>>>(W_proj, wph, Wo, woh);

    dim3 gg(Dsz / 128, Msz / 128);  // (8, 128)

    gemm_h<1, __half><<<gg, 256, GSM>>>(xh, wph, headsh, freqs, nullptr);
    pv_coef_kernel<<<Bsz, 256>>>(Wp, bp, w1, b1, w2, b2);
    mix_kernel<<<Msz / 2, 256>>>();
    gemm_h<2, float><<<gg, 256, GSM>>>(headsh, woh, out, bo, xh);
    ln_kernel<<<Msz, 256>>>(out, ln_g, ln_b);
}

// round 17
// speedup vs baseline: 1.0709x; 1.0709x over previous
#include <cuda_runtime.h>
#include <cuda_fp16.h>
#include <math.h>
#include <stdint.h>

// Problem constants
#define Bsz 8
#define Ssz 2048
#define Dsz 1024
#define Hh  8
#define HDi 128
#define Pp  32
#define Msz (Bsz*Ssz)   // 16384

// Scratch (static device arrays — no allocation)
__device__ __half g_xh[(size_t)Msz*Dsz];       // 32 MB  x in fp16
__device__ __half g_headsh[(size_t)Msz*Dsz];   // 32 MB  heads fp16 (B,S,H*HD)
__device__ __half g_wph[(size_t)Dsz*Dsz];      // 2 MB   W_proj fp16
__device__ __half g_woh[(size_t)Dsz*Dsz];      // 2 MB   Wo fp16
__device__ float  g_partial[Bsz*32*Dsz];       // 32 row-chunks of 64 rows per batch
__device__ float  g_pm[Bsz*Hh*Pp];
__device__ float  g_coef[Bsz*Hh*Hh];

// ---------------- float -> half converts ----------------
__global__ void f2h_kernel(const float* __restrict__ src, __half* __restrict__ dst) {
    int i = blockIdx.x * 256 + threadIdx.x;     // float4 index
    float4 v = reinterpret_cast<const float4*>(src)[i];
    __half2* d = reinterpret_cast<__half2*>(dst);
    d[2*i]   = __floats2half2_rn(v.x, v.y);
    d[2*i+1] = __floats2half2_rn(v.z, v.w);
}
// both weights in one launch: blocks [0,1024) -> W_proj, [1024,2048) -> Wo
__global__ void f2h_w_kernel(const float* __restrict__ s0, __half* __restrict__ d0,
                             const float* __restrict__ s1, __half* __restrict__ d1) {
    int blk = blockIdx.x;
    const float* src = (blk < 1024) ? s0 : s1;
    __half* dst      = (blk < 1024) ? d0 : d1;
    int i = (blk & 1023) * 256 + threadIdx.x;
    float4 v = reinterpret_cast<const float4*>(src)[i];
    __half2* d = reinterpret_cast<__half2*>(dst);
    d[2*i]   = __floats2half2_rn(v.x, v.y);
    d[2*i+1] = __floats2half2_rn(v.z, v.w);
}

// ====== fp16 TC GEMM: 128x128x64 block, 64x32 warp, mbarrier free-running 3-ring ======
// C[m,n] = sum_k A[m,k]*B[n,k]  (NT, fp16 operands in gmem)
// EPI==1: C half  = acc * cospi(e0[n]);  also emits column partial sums -> g_partial
// EPI==2: C float = acc + e0[n] + half2float(e1h[m,n])
#define NST 3                             // ring stages
#define BKH 64                            // K halves per stage
#define LDW 36                            // padded row stride in 32-bit words
#define STW (128*LDW)                     // words per array per stage (4608)
#define BAR_OFF ((NST*2*STW + 128) * 4)   // byte offset of mbarriers
#define GSM (BAR_OFF + 48)                // + 6 mbarriers = 111152 B

__device__ __forceinline__ void cp16(uint32_t s, const void* g) {
    asm volatile("cp.async.cg.shared.global [%0], [%1], 16;\n" :: "r"(s), "l"(g));
}
__device__ __forceinline__ void ldsm4(uint32_t& r0, uint32_t& r1, uint32_t& r2, uint32_t& r3,
                                      uint32_t addr) {
    asm volatile("ldmatrix.sync.aligned.m8n8.x4.shared.b16 {%0,%1,%2,%3}, [%4];"
                 : "=r"(r0), "=r"(r1), "=r"(r2), "=r"(r3) : "r"(addr));
}
#define MBAR_INIT(a, c) \
    asm volatile("mbarrier.init.shared.b64 [%0], %1;" :: "r"(a), "r"(c) : "memory")
#define MBAR_ARRIVE(a) \
    asm volatile("mbarrier.arrive.shared.b64 _, [%0];" :: "r"(a) : "memory")
#define CP_MBAR_ARRIVE(a) \
    asm volatile("cp.async.mbarrier.arrive.noinc.shared.b64 [%0];" :: "r"(a) : "memory")
__device__ __forceinline__ void mbar_wait(uint32_t addr, uint32_t parity) {
    asm volatile(
        "{\n\t.reg .pred P;\n\t"
        "W%=:\n\t"
        "mbarrier.try_wait.parity.shared.b64 P, [%0], %1;\n\t"
        "@P bra D%=;\n\t"
        "bra W%=;\n\t"
        "D%=:\n\t}"
        :: "r"(addr), "r"(parity) : "memory");
}

template<int EPI, typename OutT>
__global__ void __launch_bounds__(256, 2) gemm_h(
    const __half* __restrict__ A, const __half* __restrict__ Bm,
    OutT* __restrict__ C, const float* __restrict__ e0,
    const __half* __restrict__ e1h)
{
    extern __shared__ uint32_t sm[];
    float* vec = reinterpret_cast<float*>(sm + NST * 2 * STW);

    const int tid  = threadIdx.x;
    const int lane = tid & 31;
    const int w    = tid >> 5;
    const int g    = lane >> 2;
    const int tg   = lane & 3;
    const int wm   = (w >> 2) * 64;
    const int wn   = (w & 3) * 32;
    const int bm   = blockIdx.y * 128;
    const int bn   = blockIdx.x * 128;

    const uint32_t smb  = (uint32_t)__cvta_generic_to_shared(sm);
    const uint32_t barb = smb + BAR_OFF;          // full[s]=barb+8s, empty[s]=barb+24+8s

    if (tid == 0) {
        #pragma unroll
        for (int s = 0; s < NST; s++) {
            MBAR_INIT(barb + s * 8, 256);
            MBAR_INIT(barb + 24 + s * 8, 256);
        }
    }
    if (tid < 128) {
        float v = e0[bn + tid];
        vec[tid] = (EPI == 1) ? cospif(v) : v;
    }
    __syncthreads();   // only block-wide sync

    // loader: 1024 16B-chunks per array per stage; 4 per thread
    auto load_stage = [&](int kt, int s) {
        const uint32_t sA = smb + (uint32_t)(s * 2 * STW) * 4;
        const uint32_t sB = sA + (uint32_t)STW * 4;
        #pragma unroll
        for (int l = 0; l < 4; l++) {
            const int chunk = tid + l * 256;
            const int r = chunk >> 3;
            const int c = chunk & 7;
            const uint32_t so = (uint32_t)(r * LDW + c * 4) * 4;
            const size_t ko = (size_t)kt * BKH + c * 8;
            cp16(sA + so, A  + (size_t)(bm + r) * Dsz + ko);
            cp16(sB + so, Bm + (size_t)(bn + r) * Dsz + ko);
        }
    };

    // ldmatrix per-lane word offsets
    const int l8  = lane & 7;
    const int grp = lane >> 3;   // 0..3
    uint32_t aoff[4], boff[2];
    #pragma unroll
    for (int mf = 0; mf < 4; mf++) {
        const int row = wm + mf * 16 + l8 + (grp & 1) * 8;
        aoff[mf] = (uint32_t)(row * LDW + (grp >> 1) * 4) * 4;
    }
    #pragma unroll
    for (int p = 0; p < 2; p++) {
        const int row = wn + p * 16 + l8 + (grp >> 1) * 8;
        boff[p] = (uint32_t)(row * LDW + (grp & 1) * 4) * 4;
    }

    float acc[4][4][4];
    #pragma unroll
    for (int i = 0; i < 4; i++)
        #pragma unroll
        for (int j = 0; j < 4; j++)
            #pragma unroll
            for (int q = 0; q < 4; q++) acc[i][j][q] = 0.f;

    // prologue
    load_stage(0, 0); CP_MBAR_ARRIVE(barb + 0 * 8);
    load_stage(1, 1); CP_MBAR_ARRIVE(barb + 1 * 8);

    for (int kt = 0; kt < 16; kt++) {
        const int s = kt % NST;
        mbar_wait(barb + s * 8, (kt / NST) & 1);       // full[s]

        const uint32_t stA = smb + (uint32_t)(s * 2 * STW) * 4;
        const uint32_t stB = stA + (uint32_t)STW * 4;

        #pragma unroll
        for (int kk = 0; kk < 4; kk++) {
            const uint32_t kbb = kk * 32;
            uint32_t a[4][4], b[4][2];
            #pragma unroll
            for (int mf = 0; mf < 4; mf++)
                ldsm4(a[mf][0], a[mf][1], a[mf][2], a[mf][3], stA + aoff[mf] + kbb);
            #pragma unroll
            for (int p = 0; p < 2; p++)
                ldsm4(b[2*p][0], b[2*p][1], b[2*p+1][0], b[2*p+1][1], stB + boff[p] + kbb);
            #pragma unroll
            for (int mf = 0; mf < 4; mf++)
                #pragma unroll
                for (int nf = 0; nf < 4; nf++) {
                    asm volatile(
                        "mma.sync.aligned.m16n8k16.row.col.f32.f16.f16.f32 "
                        "{%0,%1,%2,%3}, {%4,%5,%6,%7}, {%8,%9}, {%0,%1,%2,%3};\n"
                        : "+f"(acc[mf][nf][0]), "+f"(acc[mf][nf][1]),
                          "+f"(acc[mf][nf][2]), "+f"(acc[mf][nf][3])
                        : "r"(a[mf][0]), "r"(a[mf][1]), "r"(a[mf][2]), "r"(a[mf][3]),
                          "r"(b[nf][0]), "r"(b[nf][1]));
                }
        }

        MBAR_ARRIVE(barb + 24 + s * 8);                // empty[s]

        const int kl = kt + 2;
        if (kl < 16) {
            const int sl = kl % NST;
            if (kl >= NST)
                mbar_wait(barb + 24 + sl * 8, ((kl / NST) - 1) & 1);
            load_stage(kl, sl);
            CP_MBAR_ARRIVE(barb + sl * 8);
        }
    }

    // ---- epilogue ----
    #pragma unroll
    for (int mf = 0; mf < 4; mf++) {
        const int r0 = bm + wm + mf * 16 + g;
        #pragma unroll
        for (int nf = 0; nf < 4; nf++) {
            const int cl = wn + nf * 8 + 2 * tg;
            const int cg = bn + cl;
            const float s0 = vec[cl], s1 = vec[cl + 1];
            if (EPI == 1) {
                __half2* Ch = reinterpret_cast<__half2*>(C);
                __half2 h0 = __floats2half2_rn(acc[mf][nf][0] * s0, acc[mf][nf][1] * s1);
                __half2 h1 = __floats2half2_rn(acc[mf][nf][2] * s0, acc[mf][nf][3] * s1);
                Ch[((size_t)r0 * Dsz + cg) >> 1]       = h0;
                Ch[((size_t)(r0 + 8) * Dsz + cg) >> 1] = h1;
            } else {
                float2 x0 = __half22float2(
                    *reinterpret_cast<const __half2*>(&e1h[(size_t)r0 * Dsz + cg]));
                float2 x1 = __half22float2(
                    *reinterpret_cast<const __half2*>(&e1h[(size_t)(r0 + 8) * Dsz + cg]));
                float2 v0, v1;
                v0.x = acc[mf][nf][0] + s0 + x0.x; v0.y = acc[mf][nf][1] + s1 + x0.y;
                v1.x = acc[mf][nf][2] + s0 + x1.x; v1.y = acc[mf][nf][3] + s1 + x1.y;
                *reinterpret_cast<float2*>(&((float*)C)[(size_t)r0 * Dsz + cg])       = v0;
                *reinterpret_cast<float2*>(&((float*)C)[(size_t)(r0 + 8) * Dsz + cg]) = v1;
            }
        }
    }

    if (EPI == 1) {
        // ---- fused hm partial sums: per-column sums of this warp's 64 rows ----
        #pragma unroll
        for (int nf = 0; nf < 4; nf++) {
            const int cl = wn + nf * 8 + 2 * tg;
            float c0 = 0.f, c1 = 0.f;
            #pragma unroll
            for (int mf = 0; mf < 4; mf++) {
                c0 += acc[mf][nf][0] + acc[mf][nf][2];
                c1 += acc[mf][nf][1] + acc[mf][nf][3];
            }
            c0 *= vec[cl]; c1 *= vec[cl + 1];
            #pragma unroll
            for (int o = 4; o < 32; o <<= 1) {
                c0 += __shfl_xor_sync(0xffffffffu, c0, o);
                c1 += __shfl_xor_sync(0xffffffffu, c1, o);
            }
            if (g == 0) {   // lanes 0..3 hold full 64-row sums
                const int b      = bm >> 11;
                const int chunk  = ((bm & 2047) >> 7) * 2 + (wm >> 6);  // 0..31
                float* dst = &g_partial[((size_t)(b * 32 + chunk)) * Dsz + bn + cl];
                dst[0] = c0;
                dst[1] = c1;
            }
        }
    }
}

// ---------------- pv (+hm reduce): grid 64 = (b*8+h), 128 threads ----------------
__global__ void pv_kernel(const float* __restrict__ Wp, const float* __restrict__ bp) {
    __shared__ float hm_s[HDi];
    __shared__ float pvs[Pp];
    const int bh = blockIdx.x;
    const int b = bh >> 3, h = bh & 7;
    const int t = threadIdx.x;

    {   // hm for this (b,h): reduce 32 partial chunks for 128 dims
        float s = 0.f;
        #pragma unroll
        for (int ch = 0; ch < 32; ch++)
            s += g_partial[((size_t)(b * 32 + ch)) * Dsz + h * HDi + t];
        hm_s[t] = s * (1.0f / Ssz);
    }
    __syncthreads();

    const int p = t >> 2, q = t & 3;
    const float* wr = &Wp[(size_t)(h * Pp + p) * HDi + q * 32];
    float s = 0.f;
    #pragma unroll 8
    for (int e = 0; e < 32; e++) s += hm_s[q * 32 + e] * wr[e];
    s += __shfl_xor_sync(0xffffffffu, s, 1);
    s += __shfl_xor_sync(0xffffffffu, s, 2);
    if (q == 0) pvs[p] = tanhf(s + bp[h * Pp + p]);
    __syncthreads();
    if (t < 32) {
        float v = pvs[t];
        float sq = v * v;
        #pragma unroll
        for (int o = 16; o > 0; o >>= 1) sq += __shfl_xor_sync(0xffffffffu, sq, o);
        float inv = 1.0f / fmaxf(sqrtf(sq), 1e-12f);
        g_pm[bh * Pp + t] = v * inv;
    }
}

// ---------------- coef: grid 8, 64 threads ----------------
__global__ void coefb_kernel(const float* __restrict__ w1, const float* __restrict__ b1,
                             const float* __restrict__ w2, const float* __restrict__ b2) {
    const int b = blockIdx.x;
    const int t = threadIdx.x;           // 64
    const int i = t >> 3, j = t & 7;
    const float* pi = &g_pm[(b * Hh + i) * Pp];
    const float* pj = &g_pm[(b * Hh + j) * Pp];
    float d = 0.f;
    #pragma unroll
    for (int p = 0; p < Pp; p++) d += pi[p] * pj[p];
    float accv = b2[0];
    #pragma unroll
    for (int k = 0; k < 16; k++) {
        float hx = d * w1[k] + b1[k];
        float gg = 0.5f * hx * (1.0f + erff(hx * 0.70710678118654752f));
        accv += gg * w2[k];
    }
    float sp = fmaxf(accv, 0.f) + log1pf(expf(-fabsf(accv)));
    g_coef[b * 64 + t] = (i == j) ? 0.f : 0.1f / (1.0f + sp);
}

// ---------------- in-place cross-head mix on fp16 heads ----------------
__global__ void mix_kernel() {
    __shared__ float cs[64];
    int m0 = blockIdx.x * 2;
    int b = m0 / Ssz;
    int t = threadIdx.x;
    if (t < 64) cs[t] = g_coef[b * 64 + t];
    __syncthreads();
    int lr = t >> 7, e = t & 127;
    int m = m0 + lr;
    int s = m & (Ssz - 1);
    float scale = (float)(s + 1) * (1.0f / (float)Ssz);
    __half* row = &g_headsh[(size_t)m * Dsz + e];
    float v[8];
    #pragma unroll
    for (int j = 0; j < 8; j++) v[j] = __half2float(row[j * HDi]);
    #pragma unroll
    for (int i = 0; i < 8; i++) {
        float a = 0.f;
        #pragma unroll
        for (int j = 0; j < 8; j++) a += cs[i * 8 + j] * v[j];
        row[i * HDi] = __float2half(v[i] + scale * a);
    }
}

// ---------------- in-place LayerNorm over D on d_out ----------------
__global__ void ln_kernel(float* __restrict__ y,
                          const float* __restrict__ g, const float* __restrict__ bb)
{
    int m = blockIdx.x;
    int t = threadIdx.x;
    float4 v = *reinterpret_cast<float4*>(&y[(size_t)m * Dsz + t * 4]);
    float s = v.x + v.y + v.z + v.w;
    float q = v.x * v.x + v.y * v.y + v.z * v.z + v.w * v.w;
    __shared__ float ss[8], qq[8];
    #pragma unroll
    for (int o = 16; o > 0; o >>= 1) {
        s += __shfl_down_sync(0xffffffffu, s, o);
        q += __shfl_down_sync(0xffffffffu, q, o);
    }
    if ((t & 31) == 0) { ss[t >> 5] = s; qq[t >> 5] = q; }
    __syncthreads();
    if (t < 8) {
        s = ss[t]; q = qq[t];
        #pragma unroll
        for (int o = 4; o > 0; o >>= 1) {
            s += __shfl_down_sync(0xffu, s, o);
            q += __shfl_down_sync(0xffu, q, o);
        }
        if (t == 0) { ss[0] = s; qq[0] = q; }
    }
    __syncthreads();
    float mu  = ss[0] * (1.0f / Dsz);
    float var = qq[0] * (1.0f / Dsz) - mu * mu;
    float inv = rsqrtf(var + 1e-5f);
    float4 gg = *reinterpret_cast<const float4*>(&g[t * 4]);
    float4 bv = *reinterpret_cast<const float4*>(&bb[t * 4]);
    v.x = (v.x - mu) * inv * gg.x + bv.x;
    v.y = (v.y - mu) * inv * gg.y + bv.y;
    v.z = (v.z - mu) * inv * gg.z + bv.z;
    v.w = (v.w - mu) * inv * gg.w + bv.w;
    *reinterpret_cast<float4*>(&y[(size_t)m * Dsz + t * 4]) = v;
}

// ======================= launch =======================
extern "C" void kernel_launch(void* const* d_in, const int* in_sizes, int n_in,
                              void* d_out, int out_size)
{
    const float* x      = (const float*)d_in[0];
    const float* W_proj = (const float*)d_in[1];
    const float* freqs  = (const float*)d_in[2];
    const float* Wp     = (const float*)d_in[3];
    const float* bp     = (const float*)d_in[4];
    const float* w1     = (const float*)d_in[5];
    const float* b1     = (const float*)d_in[6];
    const float* w2     = (const float*)d_in[7];
    const float* b2     = (const float*)d_in[8];
    const float* Wo     = (const float*)d_in[9];
    const float* bo     = (const float*)d_in[10];
    const float* ln_g   = (const float*)d_in[11];
    const float* ln_b   = (const float*)d_in[12];
    float* out = (float*)d_out;

    __half *xh = nullptr, *headsh = nullptr, *wph = nullptr, *woh = nullptr;
    cudaGetSymbolAddress((void**)&xh, g_xh);
    cudaGetSymbolAddress((void**)&headsh, g_headsh);
    cudaGetSymbolAddress((void**)&wph, g_wph);
    cudaGetSymbolAddress((void**)&woh, g_woh);

    cudaFuncSetAttribute(gemm_h<1, __half>, cudaFuncAttributeMaxDynamicSharedMemorySize, GSM);
    cudaFuncSetAttribute(gemm_h<2, float>,  cudaFuncAttributeMaxDynamicSharedMemorySize, GSM);

    // converts (x; both weights in one launch)
    f2h_kernel<<<(Msz * Dsz) / 4 / 256, 256>>>(x, xh);
    f2h_w_kernel<<<2048, 256>>>(W_proj, wph, Wo, woh);

    dim3 gg(Dsz / 128, Msz / 128);  // (8, 128)

    gemm_h<1, __half><<<gg, 256, GSM>>>(xh, wph, headsh, freqs, nullptr);
    pv_kernel<<<Bsz * Hh, 128>>>(Wp, bp);
    coefb_kernel<<<Bsz, 64>>>(w1, b1, w2, b2);
    mix_kernel<<<Msz / 2, 256>>>();
    gemm_h<2, float><<<gg, 256, GSM>>>(headsh, woh, out, bo, xh);
    ln_kernel<<<Msz, 256>>>(out, ln_g, ln_b);
}